// round 16
// baseline (speedup 1.0000x reference)
#include <cuda_runtime.h>
#include <cuda_bf16.h>
#include <cstdint>

// LayerProperties: per-channel 4->64->64->3 MLP x2 variants + epilogue.
// Round 12: variant-fused mainloop. 256 thr/CTA, warp tile = 16 rows x 64 cols,
// BOTH variants' accumulators live (64 regs) so each B fragment / W1 column /
// layer-1 partial is loaded+computed ONCE and feeds both variants' MMAs.
// Epilogue layer-3 uses packed fma.rn.f32x2 with pre-paired W3.

#define NCHAN 29
#define HID   64

typedef unsigned long long ull;

__device__ __forceinline__ float elu_f(float x) {
    return x > 0.0f ? x : (__expf(x) - 1.0f);
}
__device__ __forceinline__ float softplus_f(float x) {
    return fmaxf(x, 0.0f) + log1pf(__expf(-fabsf(x)));
}
__device__ __forceinline__ uint32_t to_tf32(float x) {
    uint32_t r;
    asm("cvt.rna.tf32.f32 %0, %1;" : "=r"(r) : "f"(x));
    return r;
}
__device__ __forceinline__ ull fma2(ull a, ull b, ull c) {
    ull d;
    asm("fma.rn.f32x2 %0, %1, %2, %3;" : "=l"(d) : "l"(a), "l"(b), "l"(c));
    return d;
}
__device__ __forceinline__ ull pack2(float lo, float hi) {
    ull d;
    asm("mov.b64 %0, {%1, %2};" : "=l"(d) : "f"(lo), "f"(hi));
    return d;
}
__device__ __forceinline__ float2 unpack2(ull p) {
    float lo, hi;
    asm("mov.b64 {%0, %1}, %2;" : "=f"(lo), "=f"(hi) : "l"(p));
    return make_float2(lo, hi);
}

__device__ __forceinline__ void mma_tf32(float d[4],
                                         uint32_t a0, uint32_t a1, uint32_t a2, uint32_t a3,
                                         uint32_t b0, uint32_t b1) {
    asm volatile(
        "mma.sync.aligned.m16n8k8.row.col.f32.tf32.tf32.f32 "
        "{%0,%1,%2,%3}, {%4,%5,%6,%7}, {%8,%9}, {%0,%1,%2,%3};"
        : "+f"(d[0]), "+f"(d[1]), "+f"(d[2]), "+f"(d[3])
        : "r"(a0), "r"(a1), "r"(a2), "r"(a3), "r"(b0), "r"(b1));
}

__global__ __launch_bounds__(256, 2) void mlp_kernel(
    const float* __restrict__ tau_g,
    const float* __restrict__ tau_lw,
    const float* __restrict__ tau_iw,
    const float* __restrict__ mu,
    const float* __restrict__ mu_bar,
    const float* __restrict__ W1,   // [NC, 4, 64]
    const float* __restrict__ b1,   // [NC, 64]
    const float* __restrict__ W2,   // [NC, 64, 64]  (W2[i][n]: i=input, n=output)
    const float* __restrict__ b2,   // [NC, 64]
    const float* __restrict__ W3,   // [NC, 64, 3]
    const float* __restrict__ b3,   // [NC, 3]
    float* __restrict__ out,        // [B, NC, 8]
    int B)
{
    __shared__ uint2  BF[2048];          // [ks=8][nt=8][lane=32], 16 KB
    __shared__ float4 W1Ts[HID];         // (W1[0][c],W1[1][c],W1[2][c],W1[3][c])
    __shared__ ull    W3x[32], W3y[32], W3z[32];  // W3 output o, col pair (2c,2c+1)
    __shared__ float  b1s[HID], b2s[HID], b3s[3];
    __shared__ float  inTG[128], inTL[128], inTI[128], inM[128], inMB[128];

    const int tid  = threadIdx.x;
    const int wid  = tid >> 5;
    const int lane = tid & 31;
    const int k    = blockIdx.x;

    // ---- stage B (W2 in tf32, fragment order), once per CTA ----
    {
        const float* W2g = W2 + (size_t)k * HID * HID;
        #pragma unroll
        for (int rep = 0; rep < 8; rep++) {
            const int e  = rep * 256 + tid;
            const int el = e & 31;
            const int nt = (e >> 5) & 7;
            const int ks = e >> 8;            // 0..7
            const int gg = el >> 2;
            const int cc = el & 3;
            const int n  = nt * 8 + gg;
            BF[e] = make_uint2(to_tf32(W2g[(ks * 8 + cc) * HID + n]),
                               to_tf32(W2g[(ks * 8 + cc + 4) * HID + n]));
        }
    }
    if (tid < HID) {
        const float* w1g = W1 + (size_t)k * 4 * HID;
        W1Ts[tid] = make_float4(w1g[tid], w1g[HID + tid], w1g[2 * HID + tid], w1g[3 * HID + tid]);
        b1s[tid] = b1[k * HID + tid];
        b2s[tid] = b2[k * HID + tid];
    }
    if (tid < 32) {
        const float* w3g = W3 + (size_t)k * HID * 3;
        W3x[tid] = pack2(w3g[(2 * tid) * 3 + 0], w3g[(2 * tid + 1) * 3 + 0]);
        W3y[tid] = pack2(w3g[(2 * tid) * 3 + 1], w3g[(2 * tid + 1) * 3 + 1]);
        W3z[tid] = pack2(w3g[(2 * tid) * 3 + 2], w3g[(2 * tid + 1) * 3 + 2]);
    }
    if (tid < 3) b3s[tid] = b3[k * 3 + tid];

    // ---- stage this CTA's 128 samples' inputs + write transmittances ----
    if (tid < 128) {
        const int b_raw = blockIdx.y * 128 + tid;
        const int b = (b_raw < B) ? b_raw : (B - 1);
        const int idx_in = b * NCHAN + k;
        const float tg = tau_g[idx_in];
        const float tl = tau_lw[idx_in];
        const float ti = tau_iw[idx_in];
        const float m  = mu[b];
        const float mb = mu_bar[b];
        inTG[tid] = tg; inTL[tid] = tl; inTI[tid] = ti; inM[tid] = m; inMB[tid] = mb;
        if (b_raw < B) {
            const float tau_tot = tg + tl + ti;
            const float t_dir = __expf(-tau_tot / (m + 1e-5f));
            const float t_dif = __expf(-tau_tot / (mb + 1e-3f));
            *reinterpret_cast<float2*>(out + (size_t)idx_in * 8) = make_float2(t_dir, t_dif);
        }
    }
    __syncthreads();   // the ONLY barrier

    const int g  = lane >> 2;        // fragment group row 0..7
    const int cq = lane & 3;         // quad col index 0..3

    // ---- this warp covers rows [wid*16, wid*16+16); thread's two rows: g, g+8 ----
    const int r0 = wid * 16 + g;
    const int r1 = r0 + 8;
    const float tg0 = inTG[r0], tl0 = inTL[r0], ti0 = inTI[r0], m0 = inM[r0], mb0 = inMB[r0];
    const float tg1 = inTG[r1], tl1 = inTL[r1], ti1 = inTI[r1], m1 = inM[r1], mb1 = inMB[r1];

    // ---- acc init from b2 (shared across variants) ----
    float acc[2][8][4];
    #pragma unroll
    for (int nt = 0; nt < 8; nt++) {
        const float cA = b2s[nt * 8 + cq * 2];
        const float cB = b2s[nt * 8 + cq * 2 + 1];
        #pragma unroll
        for (int v = 0; v < 2; v++) {
            acc[v][nt][0] = cA; acc[v][nt][1] = cB;
            acc[v][nt][2] = cA; acc[v][nt][3] = cB;
        }
    }

    // ---- fused mainloop: shared W1/B loads + layer-1 partials, both variants' MMAs ----
    #pragma unroll
    for (int ks = 0; ks < 8; ks++) {
        const int c0 = ks * 8 + cq;
        const int c1 = c0 + 4;
        const float4 w0  = W1Ts[c0];
        const float4 w1c = W1Ts[c1];
        const float bb0 = b1s[c0];
        const float bb1 = b1s[c1];

        // shared partials (tg,tl,ti terms) for rows {0,1} x cols {c0,c1}
        float sb00 = fmaf(tg0, w0.x, bb0);  sb00 = fmaf(tl0, w0.y, sb00);  sb00 = fmaf(ti0, w0.z, sb00);
        float sb10 = fmaf(tg1, w0.x, bb0);  sb10 = fmaf(tl1, w0.y, sb10);  sb10 = fmaf(ti1, w0.z, sb10);
        float sb01 = fmaf(tg0, w1c.x, bb1); sb01 = fmaf(tl0, w1c.y, sb01); sb01 = fmaf(ti0, w1c.z, sb01);
        float sb11 = fmaf(tg1, w1c.x, bb1); sb11 = fmaf(tl1, w1c.y, sb11); sb11 = fmaf(ti1, w1c.z, sb11);

        uint32_t af[2][4];
        #pragma unroll
        for (int v = 0; v < 2; v++) {
            const float x30 = v ? mb0 : m0;
            const float x31 = v ? mb1 : m1;
            af[v][0] = __float_as_uint(elu_f(fmaf(x30, w0.w,  sb00)));
            af[v][1] = __float_as_uint(elu_f(fmaf(x31, w0.w,  sb10)));
            af[v][2] = __float_as_uint(elu_f(fmaf(x30, w1c.w, sb01)));
            af[v][3] = __float_as_uint(elu_f(fmaf(x31, w1c.w, sb11)));
        }

        #pragma unroll
        for (int nt = 0; nt < 8; nt++) {
            const uint2 Bf = BF[(ks * 8 + nt) * 32 + lane];   // one LDS.64, both variants
            mma_tf32(acc[0][nt], af[0][0], af[0][1], af[0][2], af[0][3], Bf.x, Bf.y);
            mma_tf32(acc[1][nt], af[1][0], af[1][1], af[1][2], af[1][3], Bf.x, Bf.y);
        }
    }

    // ---- epilogue: ELU(h2) . W3 (packed f32x2), quad reduce, softplus+softmax ----
    #pragma unroll
    for (int v = 0; v < 2; v++) {
        #pragma unroll
        for (int j = 0; j < 2; j++) {        // j=0 -> row g, j=1 -> row g+8
            ull zp0 = 0, zp1 = 0, zp2 = 0;
            #pragma unroll
            for (int nt = 0; nt < 8; nt++) {
                const float h0 = elu_f(acc[v][nt][2 * j + 0]);
                const float h1 = elu_f(acc[v][nt][2 * j + 1]);
                const ull hp = pack2(h0, h1);
                const int pi = nt * 4 + cq;
                zp0 = fma2(hp, W3x[pi], zp0);
                zp1 = fma2(hp, W3y[pi], zp1);
                zp2 = fma2(hp, W3z[pi], zp2);
            }
            const float2 p0 = unpack2(zp0);
            const float2 p1 = unpack2(zp1);
            const float2 p2 = unpack2(zp2);
            float z0 = p0.x + p0.y;
            float z1 = p1.x + p1.y;
            float z2 = p2.x + p2.y;
            z0 += __shfl_xor_sync(0xffffffffu, z0, 1); z0 += __shfl_xor_sync(0xffffffffu, z0, 2);
            z1 += __shfl_xor_sync(0xffffffffu, z1, 1); z1 += __shfl_xor_sync(0xffffffffu, z1, 2);
            z2 += __shfl_xor_sync(0xffffffffu, z2, 1); z2 += __shfl_xor_sync(0xffffffffu, z2, 2);

            if (cq == 0) {
                z0 = softplus_f(z0 + b3s[0]);
                z1 = softplus_f(z1 + b3s[1]);
                z2 = softplus_f(z2 + b3s[2]);
                const float zm = fmaxf(z0, fmaxf(z1, z2));
                const float e0 = __expf(z0 - zm), e1 = __expf(z1 - zm), e2 = __expf(z2 - zm);
                const float inv = 1.0f / (e0 + e1 + e2);
                const int row = wid * 16 + g + 8 * j;
                const int smp = blockIdx.y * 128 + row;
                if (smp < B) {
                    float* op = out + ((size_t)smp * NCHAN + k) * 8 + 2 + 3 * v;
                    op[0] = e0 * inv;
                    op[1] = e1 * inv;
                    op[2] = e2 * inv;
                }
            }
        }
    }
}

extern "C" void kernel_launch(void* const* d_in, const int* in_sizes, int n_in,
                              void* d_out, int out_size) {
    const float* tau_g  = (const float*)d_in[0];
    const float* tau_lw = (const float*)d_in[1];
    const float* tau_iw = (const float*)d_in[2];
    const float* mu     = (const float*)d_in[3];
    const float* mu_bar = (const float*)d_in[4];
    const float* W1     = (const float*)d_in[5];
    const float* b1     = (const float*)d_in[6];
    const float* W2     = (const float*)d_in[7];
    const float* b2     = (const float*)d_in[8];
    const float* W3     = (const float*)d_in[9];
    const float* b3     = (const float*)d_in[10];
    float* out = (float*)d_out;

    const int B = in_sizes[3];  // mu has B elements

    dim3 grid(NCHAN, (B + 127) / 128);
    mlp_kernel<<<grid, 256>>>(tau_g, tau_lw, tau_iw, mu, mu_bar,
                              W1, b1, W2, b2, W3, b3, out, B);
}

// round 17
// speedup vs baseline: 1.1391x; 1.1391x over previous
#include <cuda_runtime.h>
#include <cuda_bf16.h>
#include <cuda_fp16.h>
#include <cstdint>

// LayerProperties: per-channel 4->64->64->3 MLP x2 variants + epilogue.
// Round 16: Round-11 structure (128 thr, 4 warps, 32-row tile, variant loop outer,
// in-register A fragments, barrier-free mainloop) with:
//  - FP16 m16n8k16 mma (2048 MAC/instr): MMA count and B-loads HALVED vs tf32-k8
//  - B fragment layout identical to the Round-6-proven bf16 k16 layout
//  - packed fma.rn.f32x2 layer-3 epilogue with pre-paired W3 (Round-12-proven)

#define NCHAN 29
#define HID   64

typedef unsigned long long ull;

__device__ __forceinline__ float elu_f(float x) {
    return x > 0.0f ? x : (__expf(x) - 1.0f);
}
__device__ __forceinline__ float softplus_f(float x) {
    return fmaxf(x, 0.0f) + log1pf(__expf(-fabsf(x)));
}
// pack two fp32 -> f16x2 (lo in low half)
__device__ __forceinline__ uint32_t pack_f16(float lo, float hi) {
    uint32_t r;
    asm("cvt.rn.f16x2.f32 %0, %1, %2;" : "=r"(r) : "f"(hi), "f"(lo));
    return r;
}
__device__ __forceinline__ ull fma2(ull a, ull b, ull c) {
    ull d;
    asm("fma.rn.f32x2 %0, %1, %2, %3;" : "=l"(d) : "l"(a), "l"(b), "l"(c));
    return d;
}
__device__ __forceinline__ ull pack2(float lo, float hi) {
    ull d;
    asm("mov.b64 %0, {%1, %2};" : "=l"(d) : "f"(lo), "f"(hi));
    return d;
}
__device__ __forceinline__ float2 unpack2(ull p) {
    float lo, hi;
    asm("mov.b64 {%0, %1}, %2;" : "=f"(lo), "=f"(hi) : "l"(p));
    return make_float2(lo, hi);
}

__device__ __forceinline__ void mma_f16(float d[4],
                                        uint32_t a0, uint32_t a1, uint32_t a2, uint32_t a3,
                                        uint32_t b0, uint32_t b1) {
    asm volatile(
        "mma.sync.aligned.m16n8k16.row.col.f32.f16.f16.f32 "
        "{%0,%1,%2,%3}, {%4,%5,%6,%7}, {%8,%9}, {%0,%1,%2,%3};"
        : "+f"(d[0]), "+f"(d[1]), "+f"(d[2]), "+f"(d[3])
        : "r"(a0), "r"(a1), "r"(a2), "r"(a3), "r"(b0), "r"(b1));
}

__global__ __launch_bounds__(128, 4) void mlp_kernel(
    const float* __restrict__ tau_g,
    const float* __restrict__ tau_lw,
    const float* __restrict__ tau_iw,
    const float* __restrict__ mu,
    const float* __restrict__ mu_bar,
    const float* __restrict__ W1,   // [NC, 4, 64]
    const float* __restrict__ b1,   // [NC, 64]
    const float* __restrict__ W2,   // [NC, 64, 64]  (W2[i][n]: i=input, n=output)
    const float* __restrict__ b2,   // [NC, 64]
    const float* __restrict__ W3,   // [NC, 64, 3]
    const float* __restrict__ b3,   // [NC, 3]
    float* __restrict__ out,        // [B, NC, 8]
    int B)
{
    __shared__ uint2  BF[1024];          // [ks=4][nt=8][lane=32] f16x2 pairs, 8 KB
    __shared__ float4 W1Ts[HID];         // (W1[0][c],W1[1][c],W1[2][c],W1[3][c])
    __shared__ ull    W3x[32], W3y[32], W3z[32];  // W3 out o, col pair (2c,2c+1)
    __shared__ float  b1s[HID], b2s[HID], b3s[3];
    __shared__ float  inTG[128], inTL[128], inTI[128], inM[128], inMB[128];

    const int tid  = threadIdx.x;
    const int wid  = tid >> 5;
    const int lane = tid & 31;
    const int k    = blockIdx.x;

    // ---- stage B (W2 in f16, k16 fragment order: pairs k0/k0+1 and k0+8/k0+9) ----
    {
        const float* W2g = W2 + (size_t)k * HID * HID;
        #pragma unroll
        for (int rep = 0; rep < 8; rep++) {
            const int e  = rep * 128 + tid;      // 0..1023
            const int el = e & 31;
            const int nt = (e >> 5) & 7;
            const int ks = e >> 8;               // 0..3
            const int gg = el >> 2;
            const int cc = el & 3;
            const int n  = nt * 8 + gg;
            const int k0 = ks * 16 + cc * 2;
            BF[e] = make_uint2(pack_f16(W2g[(k0 + 0) * HID + n], W2g[(k0 + 1) * HID + n]),
                               pack_f16(W2g[(k0 + 8) * HID + n], W2g[(k0 + 9) * HID + n]));
        }
    }
    if (tid < HID) {
        const float* w1g = W1 + (size_t)k * 4 * HID;
        W1Ts[tid] = make_float4(w1g[tid], w1g[HID + tid], w1g[2 * HID + tid], w1g[3 * HID + tid]);
        b1s[tid] = b1[k * HID + tid];
        b2s[tid] = b2[k * HID + tid];
    }
    if (tid < 32) {
        const float* w3g = W3 + (size_t)k * HID * 3;
        W3x[tid] = pack2(w3g[(2 * tid) * 3 + 0], w3g[(2 * tid + 1) * 3 + 0]);
        W3y[tid] = pack2(w3g[(2 * tid) * 3 + 1], w3g[(2 * tid + 1) * 3 + 1]);
        W3z[tid] = pack2(w3g[(2 * tid) * 3 + 2], w3g[(2 * tid + 1) * 3 + 2]);
    }
    if (tid < 3) b3s[tid] = b3[k * 3 + tid];

    // ---- stage this CTA's 128 samples' inputs + write transmittances ----
    const int b_raw = blockIdx.y * 128 + tid;
    {
        const int b = (b_raw < B) ? b_raw : (B - 1);
        const int idx_in = b * NCHAN + k;
        const float tg = tau_g[idx_in];
        const float tl = tau_lw[idx_in];
        const float ti = tau_iw[idx_in];
        const float m  = mu[b];
        const float mb = mu_bar[b];
        inTG[tid] = tg; inTL[tid] = tl; inTI[tid] = ti; inM[tid] = m; inMB[tid] = mb;
        if (b_raw < B) {
            const float tau_tot = tg + tl + ti;
            const float t_dir = __expf(-tau_tot / (m + 1e-5f));
            const float t_dif = __expf(-tau_tot / (mb + 1e-3f));
            *reinterpret_cast<float2*>(out + (size_t)idx_in * 8) = make_float2(t_dir, t_dif);
        }
    }
    __syncthreads();   // the ONLY barrier

    const int g  = lane >> 2;        // fragment group row 0..7
    const int cq = lane & 3;         // quad col index 0..3

    // ---- pull the 4 source rows' inputs into registers (rows wid*32+g+8j) ----
    float rtg[4], rtl[4], rti[4], rm[4], rmb[4];
    #pragma unroll
    for (int j = 0; j < 4; j++) {
        const int r = wid * 32 + g + 8 * j;
        rtg[j] = inTG[r]; rtl[j] = inTL[r]; rti[j] = inTI[r];
        rm[j] = inM[r];   rmb[j] = inMB[r];
    }

    #pragma unroll 1
    for (int v = 0; v < 2; v++) {
        float rx3[4];
        #pragma unroll
        for (int j = 0; j < 4; j++) rx3[j] = v ? rmb[j] : rm[j];

        // ---- acc init from b2 (float2 pair load) ----
        float acc[2][8][4];
        #pragma unroll
        for (int nt = 0; nt < 8; nt++) {
            const float2 cb = reinterpret_cast<const float2*>(b2s)[nt * 4 + cq];
            #pragma unroll
            for (int mt = 0; mt < 2; mt++) {
                acc[mt][nt][0] = cb.x; acc[mt][nt][1] = cb.y;
                acc[mt][nt][2] = cb.x; acc[mt][nt][3] = cb.y;
            }
        }

        // ---- mainloop: in-register A fragments (f16), k16 steps, no barriers ----
        #pragma unroll
        for (int ks = 0; ks < 4; ks++) {
            // this thread's 4 W1 columns for the k16 step
            const int c0 = ks * 16 + 2 * cq;      // c0, c0+1, c0+8, c0+9
            const float4 wA = W1Ts[c0];
            const float4 wB = W1Ts[c0 + 1];
            const float4 wC = W1Ts[c0 + 8];
            const float4 wD = W1Ts[c0 + 9];
            const float bA = b1s[c0];
            const float bB = b1s[c0 + 1];
            const float bC = b1s[c0 + 8];
            const float bD = b1s[c0 + 9];

            uint32_t aLo[4], aHi[4];     // per row j: f16x2 (c0,c0+1) and (c0+8,c0+9)
            #pragma unroll
            for (int j = 0; j < 4; j++) {
                float sA = fmaf(rtg[j], wA.x, bA);
                sA = fmaf(rtl[j], wA.y, sA); sA = fmaf(rti[j], wA.z, sA); sA = fmaf(rx3[j], wA.w, sA);
                float sB = fmaf(rtg[j], wB.x, bB);
                sB = fmaf(rtl[j], wB.y, sB); sB = fmaf(rti[j], wB.z, sB); sB = fmaf(rx3[j], wB.w, sB);
                float sC = fmaf(rtg[j], wC.x, bC);
                sC = fmaf(rtl[j], wC.y, sC); sC = fmaf(rti[j], wC.z, sC); sC = fmaf(rx3[j], wC.w, sC);
                float sD = fmaf(rtg[j], wD.x, bD);
                sD = fmaf(rtl[j], wD.y, sD); sD = fmaf(rti[j], wD.z, sD); sD = fmaf(rx3[j], wD.w, sD);
                aLo[j] = pack_f16(elu_f(sA), elu_f(sB));
                aHi[j] = pack_f16(elu_f(sC), elu_f(sD));
            }

            #pragma unroll
            for (int nt = 0; nt < 8; nt++) {
                const uint2 Bf = BF[(ks * 8 + nt) * 32 + lane];   // one LDS.64
                // a-frag order: (row g k-lo, row g+8 k-lo, row g k-hi, row g+8 k-hi)
                mma_f16(acc[0][nt], aLo[0], aLo[1], aHi[0], aHi[1], Bf.x, Bf.y);
                mma_f16(acc[1][nt], aLo[2], aLo[3], aHi[2], aHi[3], Bf.x, Bf.y);
            }
        }

        // ---- epilogue: ELU(h2) . W3 (packed f32x2), quad reduce, softplus+softmax ----
        #pragma unroll
        for (int mt = 0; mt < 2; mt++) {
            #pragma unroll
            for (int h = 0; h < 2; h++) {    // h=0 -> row +0, h=1 -> row +8 within m-tile
                ull zp0 = 0, zp1 = 0, zp2 = 0;
                #pragma unroll
                for (int nt = 0; nt < 8; nt++) {
                    const float h0 = elu_f(acc[mt][nt][2 * h + 0]);
                    const float h1 = elu_f(acc[mt][nt][2 * h + 1]);
                    const ull hp = pack2(h0, h1);
                    const int pi = nt * 4 + cq;
                    zp0 = fma2(hp, W3x[pi], zp0);
                    zp1 = fma2(hp, W3y[pi], zp1);
                    zp2 = fma2(hp, W3z[pi], zp2);
                }
                const float2 p0 = unpack2(zp0);
                const float2 p1 = unpack2(zp1);
                const float2 p2 = unpack2(zp2);
                float z0 = p0.x + p0.y;
                float z1 = p1.x + p1.y;
                float z2 = p2.x + p2.y;
                z0 += __shfl_xor_sync(0xffffffffu, z0, 1); z0 += __shfl_xor_sync(0xffffffffu, z0, 2);
                z1 += __shfl_xor_sync(0xffffffffu, z1, 1); z1 += __shfl_xor_sync(0xffffffffu, z1, 2);
                z2 += __shfl_xor_sync(0xffffffffu, z2, 1); z2 += __shfl_xor_sync(0xffffffffu, z2, 2);

                if (cq == 0) {
                    z0 = softplus_f(z0 + b3s[0]);
                    z1 = softplus_f(z1 + b3s[1]);
                    z2 = softplus_f(z2 + b3s[2]);
                    const float zm = fmaxf(z0, fmaxf(z1, z2));
                    const float e0 = __expf(z0 - zm), e1 = __expf(z1 - zm), e2 = __expf(z2 - zm);
                    const float inv = 1.0f / (e0 + e1 + e2);
                    const int row = wid * 32 + mt * 16 + g + 8 * h;
                    const int smp = blockIdx.y * 128 + row;
                    if (smp < B) {
                        float* op = out + ((size_t)smp * NCHAN + k) * 8 + 2 + 3 * v;
                        op[0] = e0 * inv;
                        op[1] = e1 * inv;
                        op[2] = e2 * inv;
                    }
                }
            }
        }
    }
}

extern "C" void kernel_launch(void* const* d_in, const int* in_sizes, int n_in,
                              void* d_out, int out_size) {
    const float* tau_g  = (const float*)d_in[0];
    const float* tau_lw = (const float*)d_in[1];
    const float* tau_iw = (const float*)d_in[2];
    const float* mu     = (const float*)d_in[3];
    const float* mu_bar = (const float*)d_in[4];
    const float* W1     = (const float*)d_in[5];
    const float* b1     = (const float*)d_in[6];
    const float* W2     = (const float*)d_in[7];
    const float* b2     = (const float*)d_in[8];
    const float* W3     = (const float*)d_in[9];
    const float* b3     = (const float*)d_in[10];
    float* out = (float*)d_out;

    const int B = in_sizes[3];  // mu has B elements

    dim3 grid(NCHAN, (B + 127) / 128);
    mlp_kernel<<<grid, 128>>>(tau_g, tau_lw, tau_iw, mu, mu_bar,
                              W1, b1, W2, b2, W3, b3, out, B);
}